// round 6
// baseline (speedup 1.0000x reference)
#include <cuda_runtime.h>
#include <cstdint>

#define B_   16384
#define L_   50
#define NW   8          // warps per CTA
#define RPW  2          // batch rows per warp
// grid = B_ / (NW*RPW) = 1024 CTAs

// smem layout (dynamic):
//   wt   : 128*128 floats, transposed W, xor-swizzled       (65536 B)
//   his  : NW * RPW * 128 floats                            ( 8192 B)
//   sidx : NW * RPW * 52 ints                               ( 3328 B)
#define WT_FLOATS   (128 * 128)
#define HIS_FLOATS  (NW * RPW * 128)
#define SIDX_INTS   (NW * RPW * 52)
#define SMEM_BYTES  ((WT_FLOATS + HIS_FLOATS) * 4 + SIDX_INTS * 4)

// ---------------------------------------------------------------------------
// Fused kernel: stage W -> per-warp [gather 2 rows -> linear 2 rows].
// wt holds W transposed: logical wt[k][j] = W[j][k], stored with the
// float4-group swizzle  group(k,j) = (j>>2) ^ ((k>>2)&31)  so that both the
// staging stores (lanes vary k) and the compute loads (lanes vary j) are
// bank-conflict-free.
// ---------------------------------------------------------------------------
__global__ __launch_bounds__(256) void fused_kernel(
    const int*    __restrict__ entities,
    const int*    __restrict__ history,
    const int*    __restrict__ hist_len,
    const float4* __restrict__ embv,    // emb as float4, row stride 32
    const float4* __restrict__ Wv,      // W   as float4, row stride 32
    const float4* __restrict__ biasv,   // bias as float4 (32 elems)
    float4*       __restrict__ outv)    // out as float4, row stride 32
{
    extern __shared__ float sm[];
    float* wt  = sm;                        // [128][128] swizzled
    float* his = sm + WT_FLOATS;            // [NW][RPW][128]
    int*   sidx = (int*)(sm + WT_FLOATS + HIS_FLOATS);  // [NW][RPW][52]

    const int tid  = threadIdx.x;
    const int warp = tid >> 5;
    const int lane = tid & 31;

    // ---- Stage W transposed + swizzled (once per CTA) ----
    for (int t = tid; t < 128 * 32; t += 256) {
        const int j  = t >> 5;          // W row = output col
        const int kv = t & 31;          // float4 index along k
        float4 w = Wv[j * 32 + kv];
        const int g = (j >> 2) ^ kv;    // swizzled float4 group
        const int w4 = j & 3;
        wt[((4 * kv + 0) << 7) + (g << 2) + w4] = w.x;
        wt[((4 * kv + 1) << 7) + (g << 2) + w4] = w.y;
        wt[((4 * kv + 2) << 7) + (g << 2) + w4] = w.z;
        wt[((4 * kv + 3) << 7) + (g << 2) + w4] = w.w;
    }
    __syncthreads();

    float* myhis0 = his + (warp * RPW + 0) * 128;
    float* myhis1 = his + (warp * RPW + 1) * 128;
    int*   idx0   = sidx + (warp * RPW + 0) * 52;
    int*   idx1   = sidx + (warp * RPW + 1) * 52;

    const int base = (blockIdx.x * NW + warp) * RPW;

    // ---- Gather: 2 rows per warp, MLP-4 each, no cross-warp sync ----
#pragma unroll
    for (int r = 0; r < RPW; r++) {
        const int b = base + r;
        int* idx = r ? idx1 : idx0;
        const int n = hist_len[b];

        if (lane < n)      idx[lane]      = history[b * L_ + lane];
        if (lane + 32 < n) idx[lane + 32] = history[b * L_ + lane + 32];
        __syncwarp();

        float4 a0 = make_float4(0.f, 0.f, 0.f, 0.f);
        float4 a1 = a0, a2 = a0, a3 = a0;

        int l = 0;
        for (; l + 4 <= n; l += 4) {
            const long i0 = idx[l + 0];
            const long i1 = idx[l + 1];
            const long i2 = idx[l + 2];
            const long i3 = idx[l + 3];
            float4 v0 = __ldg(&embv[i0 * 32 + lane]);
            float4 v1 = __ldg(&embv[i1 * 32 + lane]);
            float4 v2 = __ldg(&embv[i2 * 32 + lane]);
            float4 v3 = __ldg(&embv[i3 * 32 + lane]);
            a0.x += v0.x; a0.y += v0.y; a0.z += v0.z; a0.w += v0.w;
            a1.x += v1.x; a1.y += v1.y; a1.z += v1.z; a1.w += v1.w;
            a2.x += v2.x; a2.y += v2.y; a2.z += v2.z; a2.w += v2.w;
            a3.x += v3.x; a3.y += v3.y; a3.z += v3.z; a3.w += v3.w;
        }
        for (; l < n; l++) {
            const long i0 = idx[l];
            float4 v0 = __ldg(&embv[i0 * 32 + lane]);
            a0.x += v0.x; a0.y += v0.y; a0.z += v0.z; a0.w += v0.w;
        }

        float4 acc;
        acc.x = (a0.x + a1.x) + (a2.x + a3.x);
        acc.y = (a0.y + a1.y) + (a2.y + a3.y);
        acc.z = (a0.z + a1.z) + (a2.z + a3.z);
        acc.w = (a0.w + a1.w) + (a2.w + a3.w);

        if (n == 0)
            acc = __ldg(&embv[(long)entities[b] * 32 + lane]);

        *(float4*)&(r ? myhis1 : myhis0)[4 * lane] = acc;
    }
    __syncwarp();

    // ---- Linear: both rows against smem W (shared W reads) ----
    // lane owns output cols j = 4*lane .. 4*lane+3
    float4 accA = make_float4(0.f, 0.f, 0.f, 0.f);
    float4 accB = make_float4(0.f, 0.f, 0.f, 0.f);

#pragma unroll 8
    for (int kv = 0; kv < 32; kv++) {
        const float4 ha = *(const float4*)&myhis0[kv * 4];  // broadcast
        const float4 hb = *(const float4*)&myhis1[kv * 4];  // broadcast
        const int g = (lane ^ kv) << 2;
#pragma unroll
        for (int c = 0; c < 4; c++) {
            const int k = kv * 4 + c;
            const float4 w = *(const float4*)&wt[(k << 7) + g];
            const float fa = (c == 0) ? ha.x : (c == 1) ? ha.y : (c == 2) ? ha.z : ha.w;
            const float fb = (c == 0) ? hb.x : (c == 1) ? hb.y : (c == 2) ? hb.z : hb.w;
            accA.x = fmaf(fa, w.x, accA.x);
            accA.y = fmaf(fa, w.y, accA.y);
            accA.z = fmaf(fa, w.z, accA.z);
            accA.w = fmaf(fa, w.w, accA.w);
            accB.x = fmaf(fb, w.x, accB.x);
            accB.y = fmaf(fb, w.y, accB.y);
            accB.z = fmaf(fb, w.z, accB.z);
            accB.w = fmaf(fb, w.w, accB.w);
        }
    }

    const float4 b4 = __ldg(&biasv[lane]);
    accA.x += b4.x; accA.y += b4.y; accA.z += b4.z; accA.w += b4.w;
    accB.x += b4.x; accB.y += b4.y; accB.z += b4.z; accB.w += b4.w;

    outv[(long)(base + 0) * 32 + lane] = accA;
    outv[(long)(base + 1) * 32 + lane] = accB;
}

// ---------------------------------------------------------------------------
extern "C" void kernel_launch(void* const* d_in, const int* in_sizes, int n_in,
                              void* d_out, int out_size)
{
    const int*   entities = (const int*)d_in[0];
    const int*   history  = (const int*)d_in[1];
    const int*   hist_len = (const int*)d_in[2];
    const float* emb      = (const float*)d_in[3];
    const float* W        = (const float*)d_in[4];
    const float* bias     = (const float*)d_in[5];
    float*       out      = (float*)d_out;

    cudaFuncSetAttribute(fused_kernel,
                         cudaFuncAttributeMaxDynamicSharedMemorySize,
                         SMEM_BYTES);
    fused_kernel<<<B_ / (NW * RPW), 256, SMEM_BYTES>>>(
        entities, history, hist_len,
        (const float4*)emb, (const float4*)W, (const float4*)bias,
        (float4*)out);
}

// round 8
// speedup vs baseline: 1.5670x; 1.5670x over previous
#include <cuda_runtime.h>
#include <cuda_bf16.h>
#include <cstdint>

#define B_  16384
#define L_  50
#define TM  64     // batch rows per linear CTA

// hs: fp32 [64][128], scalar-swizzled
#define SW(r, k)  (((r) << 7) + ((k) ^ (((r) & 7) << 2)))
// W planes: bf16x2 words [128 j][64 kp], swizzled
#define SWB(j, kp) (((j) << 6) + ((kp) ^ (((j) & 7) << 2)))

#define HS_FLOATS   (TM * 128)        // 8192
#define PLANE_WORDS (128 * 64)        // 8192
#define SMEM_BYTES  ((HS_FLOATS + 2 * PLANE_WORDS) * 4)   // 96 KB

// 8 MB scratch for the pooled history embedding [B, 128]
__device__ float g_his[B_ * 128];

// ---------------------------------------------------------------------------
// Kernel 1: masked gather-sum (unchanged; ~5.4 TB/s effective).
// ---------------------------------------------------------------------------
__global__ __launch_bounds__(256) void gather_kernel(
    const int*    __restrict__ entities,
    const int*    __restrict__ history,
    const int*    __restrict__ hist_len,
    const float4* __restrict__ embv)
{
    const int warp = threadIdx.x >> 5;
    const int lane = threadIdx.x & 31;
    const int b    = (blockIdx.x << 3) + warp;

    __shared__ int sh_idx[8][52];

    const int n = hist_len[b];
    for (int l = lane; l < n; l += 32)
        sh_idx[warp][l] = history[b * L_ + l];
    __syncwarp();

    float4 a0 = make_float4(0.f, 0.f, 0.f, 0.f);
    float4 a1 = a0, a2 = a0, a3 = a0;

    int l = 0;
    for (; l + 4 <= n; l += 4) {
        const long i0 = sh_idx[warp][l + 0];
        const long i1 = sh_idx[warp][l + 1];
        const long i2 = sh_idx[warp][l + 2];
        const long i3 = sh_idx[warp][l + 3];
        float4 v0 = __ldg(&embv[i0 * 32 + lane]);
        float4 v1 = __ldg(&embv[i1 * 32 + lane]);
        float4 v2 = __ldg(&embv[i2 * 32 + lane]);
        float4 v3 = __ldg(&embv[i3 * 32 + lane]);
        a0.x += v0.x; a0.y += v0.y; a0.z += v0.z; a0.w += v0.w;
        a1.x += v1.x; a1.y += v1.y; a1.z += v1.z; a1.w += v1.w;
        a2.x += v2.x; a2.y += v2.y; a2.z += v2.z; a2.w += v2.w;
        a3.x += v3.x; a3.y += v3.y; a3.z += v3.z; a3.w += v3.w;
    }
    for (; l < n; l++) {
        const long i0 = sh_idx[warp][l];
        float4 v0 = __ldg(&embv[i0 * 32 + lane]);
        a0.x += v0.x; a0.y += v0.y; a0.z += v0.z; a0.w += v0.w;
    }

    float4 acc;
    acc.x = (a0.x + a1.x) + (a2.x + a3.x);
    acc.y = (a0.y + a1.y) + (a2.y + a3.y);
    acc.z = (a0.z + a1.z) + (a2.z + a3.z);
    acc.w = (a0.w + a1.w) + (a2.w + a3.w);

    if (n == 0)
        acc = __ldg(&embv[(long)entities[b] * 32 + lane]);

    ((float4*)g_his)[b * 32 + lane] = acc;
}

// ---------------------------------------------------------------------------
// bf16 split helpers
// ---------------------------------------------------------------------------
__device__ __forceinline__ void split_bf16(float x, uint32_t& h, uint32_t& l) {
    uint16_t hb = __bfloat16_as_ushort(__float2bfloat16_rn(x));
    float hf = __uint_as_float(((uint32_t)hb) << 16);
    uint16_t lb = __bfloat16_as_ushort(__float2bfloat16_rn(x - hf));
    h = hb; l = lb;
}
__device__ __forceinline__ uint32_t pack2(uint32_t lo16, uint32_t hi16) {
    return (lo16 & 0xFFFFu) | (hi16 << 16);
}
__device__ __forceinline__ void mma_bf16(float c[4], const uint32_t a[4],
                                         uint32_t b0, uint32_t b1) {
    asm volatile(
        "mma.sync.aligned.m16n8k16.row.col.f32.bf16.bf16.f32 "
        "{%0,%1,%2,%3}, {%4,%5,%6,%7}, {%8,%9}, {%0,%1,%2,%3};"
        : "+f"(c[0]), "+f"(c[1]), "+f"(c[2]), "+f"(c[3])
        : "r"(a[0]), "r"(a[1]), "r"(a[2]), "r"(a[3]), "r"(b0), "r"(b1));
}

// ---------------------------------------------------------------------------
// Kernel 2: out = his @ W^T + bias via 3-pass split-bf16 mma.m16n8k16.
// CTA = 64x128 tile, 8 warps (warp = 16 rows x 64 cols).
// smem: hs fp32 [64][128] + whi/wlo bf16x2 planes [128][64] = 96KB.
// ---------------------------------------------------------------------------
__global__ __launch_bounds__(256, 2) void linear_kernel(
    const float4* __restrict__ Wv,
    const float*  __restrict__ bias,
    float*        __restrict__ out)
{
    extern __shared__ float sm[];
    float*    hs  = sm;                                  // [64][128] swizzled
    uint32_t* whi = (uint32_t*)(sm + HS_FLOATS);         // [128][64] words
    uint32_t* wlo = whi + PLANE_WORDS;

    const int tid  = threadIdx.x;
    const int lane = tid & 31;
    const int warp = tid >> 5;
    const int gq   = lane >> 2;      // 0..7
    const int tq   = lane & 3;       // 0..3
    const int wm   = warp >> 1;      // 0..3 : 16-row group
    const int wn   = warp & 1;       // 0..1 : 64-col group
    const int row0 = blockIdx.x * TM;

    const float4* hisv = (const float4*)g_his;

    // Stage his tile (raw fp32, swizzled)
    for (int t = tid; t < TM * 32; t += 256) {
        const int r  = t >> 5;
        const int kv = t & 31;
        float4 v = hisv[(long)(row0 + r) * 32 + kv];
        *(float4*)&hs[SW(r, kv * 4)] = v;
    }
    // Stage W split hi/lo as packed bf16x2 planes
    for (int t = tid; t < 128 * 32; t += 256) {
        const int j  = t >> 5;
        const int kv = t & 31;          // covers k = 4kv..4kv+3 -> kp = 2kv, 2kv+1
        float4 w = Wv[(long)j * 32 + kv];
        uint32_t h0, l0, h1, l1, h2, l2, h3, l3;
        split_bf16(w.x, h0, l0);
        split_bf16(w.y, h1, l1);
        split_bf16(w.z, h2, l2);
        split_bf16(w.w, h3, l3);
        whi[SWB(j, 2 * kv)]     = pack2(h0, h1);
        whi[SWB(j, 2 * kv + 1)] = pack2(h2, h3);
        wlo[SWB(j, 2 * kv)]     = pack2(l0, l1);
        wlo[SWB(j, 2 * kv + 1)] = pack2(l2, l3);
    }
    __syncthreads();

    // Accumulators initialized with bias.
    float c[8][4];
#pragma unroll
    for (int n = 0; n < 8; n++) {
        const int col = wn * 64 + n * 8 + 2 * tq;
        const float b0 = __ldg(&bias[col]);
        const float b1 = __ldg(&bias[col + 1]);
        c[n][0] = b0; c[n][1] = b1;
        c[n][2] = b0; c[n][3] = b1;
    }

#pragma unroll
    for (int kt = 0; kt < 8; kt++) {
        const int k0 = kt * 16;
        const int r  = wm * 16 + gq;

        // A fragment (16 rows x 16 k), split hi/lo -> packed bf16x2.
        uint32_t ahi[4], alo[4];
        {
            float x0 = hs[SW(r,     k0 + 2 * tq)];
            float x1 = hs[SW(r,     k0 + 2 * tq + 1)];
            float x2 = hs[SW(r + 8, k0 + 2 * tq)];
            float x3 = hs[SW(r + 8, k0 + 2 * tq + 1)];
            float x4 = hs[SW(r,     k0 + 2 * tq + 8)];
            float x5 = hs[SW(r,     k0 + 2 * tq + 9)];
            float x6 = hs[SW(r + 8, k0 + 2 * tq + 8)];
            float x7 = hs[SW(r + 8, k0 + 2 * tq + 9)];
            uint32_t h0,l0,h1,l1,h2,l2,h3,l3,h4,l4,h5,l5,h6,l6,h7,l7;
            split_bf16(x0, h0, l0); split_bf16(x1, h1, l1);
            split_bf16(x2, h2, l2); split_bf16(x3, h3, l3);
            split_bf16(x4, h4, l4); split_bf16(x5, h5, l5);
            split_bf16(x6, h6, l6); split_bf16(x7, h7, l7);
            ahi[0] = pack2(h0, h1); ahi[1] = pack2(h2, h3);
            ahi[2] = pack2(h4, h5); ahi[3] = pack2(h6, h7);
            alo[0] = pack2(l0, l1); alo[1] = pack2(l2, l3);
            alo[2] = pack2(l4, l5); alo[3] = pack2(l6, l7);
        }

#pragma unroll
        for (int n = 0; n < 8; n++) {
            const int j  = wn * 64 + n * 8 + gq;   // output col = W row
            const int kp = kt * 8 + tq;
            uint32_t bh0 = whi[SWB(j, kp)];
            uint32_t bh1 = whi[SWB(j, kp + 4)];
            uint32_t bl0 = wlo[SWB(j, kp)];
            uint32_t bl1 = wlo[SWB(j, kp + 4)];
            mma_bf16(c[n], ahi, bh0, bh1);   // Ah*Bh
            mma_bf16(c[n], ahi, bl0, bl1);   // Ah*Bl
            mma_bf16(c[n], alo, bh0, bh1);   // Al*Bh
        }
    }

    // Epilogue
#pragma unroll
    for (int n = 0; n < 8; n++) {
        const int r   = row0 + wm * 16 + gq;
        const int col = wn * 64 + n * 8 + 2 * tq;
        *(float2*)&out[(long)r * 128 + col]       = make_float2(c[n][0], c[n][1]);
        *(float2*)&out[(long)(r + 8) * 128 + col] = make_float2(c[n][2], c[n][3]);
    }
}

// ---------------------------------------------------------------------------
extern "C" void kernel_launch(void* const* d_in, const int* in_sizes, int n_in,
                              void* d_out, int out_size)
{
    const int*   entities = (const int*)d_in[0];
    const int*   history  = (const int*)d_in[1];
    const int*   hist_len = (const int*)d_in[2];
    const float* emb      = (const float*)d_in[3];
    const float* W        = (const float*)d_in[4];
    const float* bias     = (const float*)d_in[5];
    float*       out      = (float*)d_out;

    gather_kernel<<<B_ / 8, 256>>>(entities, history, hist_len,
                                   (const float4*)emb);

    cudaFuncSetAttribute(linear_kernel,
                         cudaFuncAttributeMaxDynamicSharedMemorySize,
                         SMEM_BYTES);
    linear_kernel<<<B_ / TM, 256, SMEM_BYTES>>>((const float4*)W, bias, out);
}